// round 16
// baseline (speedup 1.0000x reference)
#include <cuda_runtime.h>
#include <cstdint>

// MultiScaleProcessor: input [64,256,256,3] f32 -> output [64,4,256,256,3] f32
// scales = {32,64,128,256}; bilinear (linspace endpoints), zero-pad to 256.
//
// R12 TMA-bulk-store kernel + zero-block dedup:
//  - zero blocks: fill 24KB once, issue 4 bulk stores (4 pad groups each)
//  - copy blocks: LDG.128 -> STS -> bulk store (proven R12 path)
//  - compute blocks: bilinear -> staged -> bulk store
// Block exit: cp.async.bulk.wait_group.read 0 (smem-read drain only).
// No mbarrier/TMA-load machinery (suspected hang in R13/R15 runs).

#define HH 256
#define WW 256
#define NB 64
#define ROWF (WW * 3)             // 768 floats per row
#define CHUNK 8                   // rows per chunk; pads (112,96,64) %8==0
#define NT 256
#define CBYTES (CHUNK * ROWF * 4) // 24576 bytes per chunk
#define CROWV (CHUNK * ROWF / 4)  // 1536 float4 per chunk
#define VPT (CROWV / NT)          // 6 float4 per thread
#define PPT (CHUNK * WW / NT)     // 8 pixels per thread

#define N_COMP_PER_B 28           // 4 (s=32) + 8 (s=64) + 16 (s=128)
#define N_COPY_PER_B 32
#define N_ZERO_PER_B 17           // 68 zero groups / 4 per block
#define N_COMP (NB * N_COMP_PER_B)   // 1792
#define N_COPY (NB * N_COPY_PER_B)   // 2048
#define N_ZERO (NB * N_ZERO_PER_B)   // 1088

__device__ __forceinline__ uint32_t smem_u32(const void* p) {
    uint32_t a;
    asm("{ .reg .u64 t; cvta.to.shared.u64 t, %1; cvt.u32.u64 %0, t; }"
        : "=r"(a) : "l"(p));
    return a;
}

__device__ __forceinline__ void fence_async() {
    asm volatile("fence.proxy.async.shared::cta;" ::: "memory");
}

__device__ __forceinline__ void bulk_store(void* gdst, uint32_t ssrc) {
    asm volatile(
        "cp.async.bulk.global.shared::cta.bulk_group [%0], [%1], %2;"
        :: "l"(gdst), "r"(ssrc), "n"(CBYTES) : "memory");
}

__device__ __forceinline__ void commit_and_drain_read() {
    asm volatile("cp.async.bulk.commit_group;" ::: "memory");
    asm volatile("cp.async.bulk.wait_group.read 0;" ::: "memory");
}

// zero-group index k (0..67) -> (sc, cy)
__device__ __forceinline__ void zero_map(int k, int& sc, int& cy) {
    if (k < 14)      { sc = 0; cy = k; }
    else if (k < 28) { sc = 0; cy = (k - 14) + 18; }
    else if (k < 40) { sc = 1; cy = (k - 28); }
    else if (k < 52) { sc = 1; cy = (k - 40) + 20; }
    else if (k < 60) { sc = 2; cy = (k - 52); }
    else             { sc = 2; cy = (k - 60) + 24; }
}

__global__ __launch_bounds__(NT) void msp_kernel(const float* __restrict__ in,
                                                 float* __restrict__ out) {
    __shared__ __align__(16) float buf[CHUNK * ROWF];  // 24 KB staging

    const int bid = blockIdx.x;
    const int tid = threadIdx.x;

    if (bid < N_COMP) {
        // ---------------- compute block ----------------
        const int b = bid / N_COMP_PER_B;
        const int k = bid % N_COMP_PER_B;
        int sc, cy;
        if (k < 4)       { sc = 0; cy = 14 + k; }        // s=32,  rows 112..143
        else if (k < 12) { sc = 1; cy = 12 + (k - 4); }  // s=64,  rows 96..159
        else             { sc = 2; cy = 8 + (k - 12); }  // s=128, rows 64..191

        const int s  = 32 << sc;
        const int p  = (256 - s) >> 1;
        const int yc = cy * CHUNK;
        const float inv = 255.0f / (float)(s - 1);
        const float* __restrict__ base = in + (size_t)b * (HH * ROWF);

#pragma unroll
        for (int j = 0; j < PPT; j++) {
            const int pi = tid + j * NT;   // 0..2047
            const int r  = pi >> 8;        // local row 0..7
            const int x  = pi & 255;       // column 0..255
            float* dst = &buf[r * ROWF + 3 * x];
            if (x < p || x >= p + s) {
                dst[0] = 0.f; dst[1] = 0.f; dst[2] = 0.f;
            } else {
                const float fy = (float)(yc + r - p) * inv;
                const int   y0 = (int)fy;          // fy >= 0: trunc == floor
                const int   y1 = min(y0 + 1, HH - 1);
                const float wy = fy - (float)y0;

                const float fx = (float)(x - p) * inv;
                const int   x0 = (int)fx;
                const int   x1 = min(x0 + 1, WW - 1);
                const float wx = fx - (float)x0;

                const float* __restrict__ r0 = base + (size_t)y0 * ROWF;
                const float* __restrict__ r1 = base + (size_t)y1 * ROWF;
                const float wx0 = 1.f - wx;
                const float wy0 = 1.f - wy;
#pragma unroll
                for (int c = 0; c < 3; c++) {
                    const float t  = __ldg(r0 + 3 * x0 + c) * wx0 +
                                     __ldg(r0 + 3 * x1 + c) * wx;
                    const float bt = __ldg(r1 + 3 * x0 + c) * wx0 +
                                     __ldg(r1 + 3 * x1 + c) * wx;
                    dst[c] = t * wy0 + bt * wy;
                }
            }
        }
        __syncthreads();
        if (tid == 0) {
            float* gdst = out + ((((size_t)b * 4 + sc) * HH + yc) * ROWF);
            fence_async();
            bulk_store(gdst, smem_u32(buf));
            commit_and_drain_read();
        }
    } else if (bid < N_COMP + N_COPY) {
        // ---------------- copy block: LDG.128 -> STS -> bulk store ----------
        const int i  = bid - N_COMP;
        const int b  = i / N_COPY_PER_B;
        const int yc = (i % N_COPY_PER_B) * CHUNK;

        const float4* __restrict__ ichunk =
            (const float4*)(in + ((size_t)b * HH + yc) * ROWF);
        float4* const b4 = (float4*)buf;
#pragma unroll
        for (int j = 0; j < VPT; j++)
            b4[tid + j * NT] = __ldg(&ichunk[tid + j * NT]);
        __syncthreads();
        if (tid == 0) {
            float* gdst = out + ((((size_t)b * 4 + 3) * HH + yc) * ROWF);
            fence_async();
            bulk_store(gdst, smem_u32(buf));
            commit_and_drain_read();
        }
    } else {
        // ---------------- zero block: fill once, store 4x ----------------
        const int i  = bid - N_COMP - N_COPY;
        const int b  = i / N_ZERO_PER_B;
        const int k0 = (i % N_ZERO_PER_B) * 4;   // 4 consecutive zero groups

        const float4 z = make_float4(0.f, 0.f, 0.f, 0.f);
        float4* const b4 = (float4*)buf;
#pragma unroll
        for (int j = 0; j < VPT; j++)
            b4[tid + j * NT] = z;
        __syncthreads();

        if (tid == 0) {
            const uint32_t sa = smem_u32(buf);
            fence_async();
#pragma unroll
            for (int g = 0; g < 4; g++) {
                int sc, cy;
                zero_map(k0 + g, sc, cy);
                float* gdst =
                    out + ((((size_t)b * 4 + sc) * HH + cy * CHUNK) * ROWF);
                bulk_store(gdst, sa);
            }
            commit_and_drain_read();
        }
    }
}

extern "C" void kernel_launch(void* const* d_in, const int* in_sizes, int n_in,
                              void* d_out, int out_size) {
    const float* in  = (const float*)d_in[0];
    float*       out = (float*)d_out;
    (void)in_sizes; (void)n_in; (void)out_size;

    msp_kernel<<<N_COMP + N_COPY + N_ZERO, NT>>>(in, out);
}